// round 4
// baseline (speedup 1.0000x reference)
#include <cuda_runtime.h>

// SelfAttention: B=16, E=42, n=E*E=1764 tokens, D=256.
// out[b,n,:256] = x ; out[b,n,256:] = softmax(x*dot_scale @ m^T + mask_bias) @ m
// (input_dot = x @ w_lin^T is constant along the softmax axis -> cancels; w_lin unused)

#define NB      16
#define NE      42
#define NTOK    (NE*NE)     // 1764
#define DD      256
#define BM      64          // query rows per CTA
#define BN      64          // keys per inner tile
#define QP      68          // padded pitch for transposed smem tiles (gcd(68,32)=4 -> 8 banks)
#define NQT     28          // ceil(1764/64)
#define NKT     28
#define NTHREADS 256

__device__ int g_mask_is4;  // 1 if mask elements are 4 bytes wide, 0 if 1 byte

// ---------------------------------------------------------------------------
// packed fp32x2 helpers (Blackwell FFMA2: 2x fp32 FMA throughput vs scalar FFMA)
// ---------------------------------------------------------------------------
__device__ __forceinline__ unsigned long long pk2(float a, float b) {
    unsigned long long r;
    asm("mov.b64 %0, {%1, %2};" : "=l"(r) : "f"(a), "f"(b));
    return r;
}
__device__ __forceinline__ void upk2(unsigned long long v, float& a, float& b) {
    asm("mov.b64 {%0, %1}, %2;" : "=f"(a), "=f"(b) : "l"(v));
}
__device__ __forceinline__ void ffma2(unsigned long long& d, unsigned long long a,
                                      unsigned long long b) {
    asm("fma.rn.f32x2 %0, %1, %2, %0;" : "+l"(d) : "l"(a), "l"(b));
}
__device__ __forceinline__ void fmul2(unsigned long long& d, unsigned long long a,
                                      unsigned long long b) {
    asm("mul.rn.f32x2 %0, %1, %2;" : "=l"(d) : "l"(a), "l"(b));
}

// ---------------------------------------------------------------------------
// Mask dtype detection: jax bool may arrive as 1-byte bool, int32 {0,1}, or
// float32 {0.0,1.0}. Rules on bytes [0, NB*NTOK):
//   no nonzero byte at (i%4)!=0            -> 4-byte (int32 0/1)
//   some byte outside {0,1}                -> 4-byte (float32 pattern bytes)
//   else                                   -> 1-byte bool
// In the 4-byte case "word != 0" is keep for both int32 and float32.
// ---------------------------------------------------------------------------
__global__ void detect_mask_kernel(const unsigned char* __restrict__ m, int nbytes) {
    __shared__ int sOdd, sWeird;
    if (threadIdx.x == 0) { sOdd = 0; sWeird = 0; }
    __syncthreads();
    int lodd = 0, lweird = 0;
    for (int i = threadIdx.x; i < nbytes; i += blockDim.x) {
        unsigned char v = m[i];
        if (v > 1) lweird = 1;
        if ((i & 3) && v) lodd = 1;
    }
    if (lodd) sOdd = 1;
    if (lweird) sWeird = 1;
    __syncthreads();
    if (threadIdx.x == 0) g_mask_is4 = ((sOdd == 0) || sWeird) ? 1 : 0;
}

// ---------------------------------------------------------------------------
// Flash-attention style kernel. One CTA = (batch, 64-query tile).
// Dynamic smem:
//   q_s  [DD][QP]  : x tile, transposed, pre-scaled by dot_scale
//   k_s  [DD][QP]  : m tile, transposed           (aliased with P_s [BN][QP])
//   v_s  [BN][DD]  : m tile, natural (also staging buffer for q load)
//   bias_s [BN], scale_s [DD]
// ---------------------------------------------------------------------------
__global__ void __launch_bounds__(NTHREADS, 1)
attn_kernel(const float* __restrict__ x, const float* __restrict__ mem,
            const unsigned char* __restrict__ mask8,
            const float* __restrict__ dscale, float* __restrict__ out)
{
    extern __shared__ float smem[];
    float* q_s     = smem;                 // DD*QP
    float* k_s     = smem + DD * QP;       // DD*QP (aliased with P_s)
    float* P_s     = k_s;                  // BN*QP  (<= DD*QP)
    float* v_s     = smem + 2 * DD * QP;   // BN*DD
    float* bias_s  = v_s + BN * DD;        // BN
    float* scale_s = bias_s + BN;          // DD

    const int b     = blockIdx.y;
    const int qbase = blockIdx.x * BM;
    const int tid   = threadIdx.x;
    const int tx    = tid & 15;            // column / dim-slice lane
    const int ty    = tid >> 4;            // row group
    const int r0    = ty * 4;
    const int c0    = tx * 4;
    const int dstart = tx * 16;
    const int warp  = tid >> 5;
    const int ln    = tid & 31;
    const bool is4  = (g_mask_is4 != 0);
    const int* mask32 = (const int*)mask8;

    for (int i = tid; i < DD; i += NTHREADS) scale_s[i] = dscale[i];

    // ---- load + transpose Q tile (scaled by dot_scale), staged via v_s ----
    {
        const float* xb = x + ((size_t)b * NTOK + qbase) * DD;
        for (int idx = tid; idx < BM * (DD / 4); idx += NTHREADS) {
            int d4 = idx & 63;
            int row = idx >> 6;
            float4 v = make_float4(0.f, 0.f, 0.f, 0.f);
            if (qbase + row < NTOK) v = *(const float4*)(xb + row * DD + d4 * 4);
            *(float4*)(v_s + row * DD + d4 * 4) = v;
        }
        __syncthreads();
        for (int r = warp; r < BM; r += 8) {
            #pragma unroll
            for (int d0 = 0; d0 < DD; d0 += 32) {
                int d = d0 + ln;
                q_s[d * QP + r] = v_s[r * DD + d] * scale_s[d];
            }
        }
    }

    // ---- flash accumulators ----
    unsigned long long O2[4][8];           // 4 rows x 16 dims (packed pairs)
    #pragma unroll
    for (int r = 0; r < 4; r++)
        #pragma unroll
        for (int j = 0; j < 8; j++) O2[r][j] = 0ull;
    float mrow[4] = { -1e30f, -1e30f, -1e30f, -1e30f };
    float lrow[4] = { 0.f, 0.f, 0.f, 0.f };   // per-lane partial sums (4 cols each)

    for (int kt = 0; kt < NKT; kt++) {
        const int kbase = kt * BN;
        __syncthreads();  // previous-iteration reads of v_s / P_s complete

        // ---- stage K/V tile (natural) + mask bias ----
        const float* mb = mem + ((size_t)b * NTOK + kbase) * DD;
        for (int idx = tid; idx < BN * (DD / 4); idx += NTHREADS) {
            int d4 = idx & 63;
            int row = idx >> 6;
            float4 v = make_float4(0.f, 0.f, 0.f, 0.f);
            if (kbase + row < NTOK) v = *(const float4*)(mb + row * DD + d4 * 4);
            *(float4*)(v_s + row * DD + d4 * 4) = v;
        }
        if (tid < BN) {
            int key = kbase + tid;
            float bias = -1e30f;
            if (key < NTOK) {
                int mi = b * NTOK + key;
                bool keep = is4 ? (mask32[mi] != 0) : (mask8[mi] != 0);
                if (keep) bias = 0.f;
            }
            bias_s[tid] = bias;
        }
        __syncthreads();

        // ---- transpose K into k_s[d][key] ----
        for (int r = warp; r < BN; r += 8) {
            #pragma unroll
            for (int d0 = 0; d0 < DD; d0 += 32) {
                int d = d0 + ln;
                k_s[d * QP + r] = v_s[r * DD + d];
            }
        }
        __syncthreads();

        // ---- S = Q_scaled @ K^T  (4x4 per thread, packed FFMA2) ----
        unsigned long long acc[4][2];
        #pragma unroll
        for (int r = 0; r < 4; r++) { acc[r][0] = 0ull; acc[r][1] = 0ull; }
        const float* qp = q_s + r0;
        const float* kp = k_s + c0;
        #pragma unroll 8
        for (int d = 0; d < DD; d++) {
            float4 qv = *(const float4*)(qp + d * QP);
            float4 kv = *(const float4*)(kp + d * QP);
            unsigned long long kA = pk2(kv.x, kv.y);
            unsigned long long kB = pk2(kv.z, kv.w);
            unsigned long long q0 = pk2(qv.x, qv.x);
            unsigned long long q1 = pk2(qv.y, qv.y);
            unsigned long long q2 = pk2(qv.z, qv.z);
            unsigned long long q3 = pk2(qv.w, qv.w);
            ffma2(acc[0][0], q0, kA); ffma2(acc[0][1], q0, kB);
            ffma2(acc[1][0], q1, kA); ffma2(acc[1][1], q1, kB);
            ffma2(acc[2][0], q2, kA); ffma2(acc[2][1], q2, kB);
            ffma2(acc[3][0], q3, kA); ffma2(acc[3][1], q3, kB);
        }

        // ---- bias + online softmax ----
        float s[4][4];
        #pragma unroll
        for (int r = 0; r < 4; r++) {
            upk2(acc[r][0], s[r][0], s[r][1]);
            upk2(acc[r][1], s[r][2], s[r][3]);
        }
        float bias0 = bias_s[c0 + 0], bias1 = bias_s[c0 + 1];
        float bias2 = bias_s[c0 + 2], bias3 = bias_s[c0 + 3];
        #pragma unroll
        for (int r = 0; r < 4; r++) {
            s[r][0] += bias0; s[r][1] += bias1; s[r][2] += bias2; s[r][3] += bias3;
        }
        #pragma unroll
        for (int r = 0; r < 4; r++) {
            float t = fmaxf(fmaxf(s[r][0], s[r][1]), fmaxf(s[r][2], s[r][3]));
            t = fmaxf(t, __shfl_xor_sync(0xffffffffu, t, 1));
            t = fmaxf(t, __shfl_xor_sync(0xffffffffu, t, 2));
            t = fmaxf(t, __shfl_xor_sync(0xffffffffu, t, 4));
            t = fmaxf(t, __shfl_xor_sync(0xffffffffu, t, 8));
            float mn  = fmaxf(mrow[r], t);
            float scl = __expf(mrow[r] - mn);
            mrow[r] = mn;
            float ls = 0.f;
            #pragma unroll
            for (int c = 0; c < 4; c++) {
                float p = __expf(s[r][c] - mn);
                s[r][c] = p;
                ls += p;
            }
            lrow[r] = lrow[r] * scl + ls;
            unsigned long long s2 = pk2(scl, scl);
            #pragma unroll
            for (int j = 0; j < 8; j++) fmul2(O2[r][j], O2[r][j], s2);
        }

        __syncthreads();  // everyone done reading k_s (P_s aliases it)

        // ---- write P transposed [key][row] ----
        #pragma unroll
        for (int c = 0; c < 4; c++) {
            float4 pv = make_float4(s[0][c], s[1][c], s[2][c], s[3][c]);
            *(float4*)(P_s + (c0 + c) * QP + r0) = pv;
        }
        __syncthreads();

        // ---- O += P @ V  (4 rows x 16 dims per thread) ----
        #pragma unroll 2
        for (int k = 0; k < BN; k++) {
            float4 pv = *(const float4*)(P_s + k * QP + r0);
            unsigned long long p0 = pk2(pv.x, pv.x);
            unsigned long long p1 = pk2(pv.y, pv.y);
            unsigned long long p2 = pk2(pv.z, pv.z);
            unsigned long long p3 = pk2(pv.w, pv.w);
            const ulonglong2* vp = (const ulonglong2*)(v_s + k * DD + dstart);
            ulonglong2 vA = vp[0];
            ulonglong2 vB = vp[1];
            ulonglong2 vC = vp[2];
            ulonglong2 vD = vp[3];
            ffma2(O2[0][0], p0, vA.x); ffma2(O2[0][1], p0, vA.y);
            ffma2(O2[0][2], p0, vB.x); ffma2(O2[0][3], p0, vB.y);
            ffma2(O2[0][4], p0, vC.x); ffma2(O2[0][5], p0, vC.y);
            ffma2(O2[0][6], p0, vD.x); ffma2(O2[0][7], p0, vD.y);
            ffma2(O2[1][0], p1, vA.x); ffma2(O2[1][1], p1, vA.y);
            ffma2(O2[1][2], p1, vB.x); ffma2(O2[1][3], p1, vB.y);
            ffma2(O2[1][4], p1, vC.x); ffma2(O2[1][5], p1, vC.y);
            ffma2(O2[1][6], p1, vD.x); ffma2(O2[1][7], p1, vD.y);
            ffma2(O2[2][0], p2, vA.x); ffma2(O2[2][1], p2, vA.y);
            ffma2(O2[2][2], p2, vB.x); ffma2(O2[2][3], p2, vB.y);
            ffma2(O2[2][4], p2, vC.x); ffma2(O2[2][5], p2, vC.y);
            ffma2(O2[2][6], p2, vD.x); ffma2(O2[2][7], p2, vD.y);
            ffma2(O2[3][0], p3, vA.x); ffma2(O2[3][1], p3, vA.y);
            ffma2(O2[3][2], p3, vB.x); ffma2(O2[3][3], p3, vB.y);
            ffma2(O2[3][4], p3, vC.x); ffma2(O2[3][5], p3, vC.y);
            ffma2(O2[3][6], p3, vD.x); ffma2(O2[3][7], p3, vD.y);
        }
    }

    // ---- finalize: total l across the 16 column lanes, normalize, store ----
    #pragma unroll
    for (int r = 0; r < 4; r++) {
        lrow[r] += __shfl_xor_sync(0xffffffffu, lrow[r], 1);
        lrow[r] += __shfl_xor_sync(0xffffffffu, lrow[r], 2);
        lrow[r] += __shfl_xor_sync(0xffffffffu, lrow[r], 4);
        lrow[r] += __shfl_xor_sync(0xffffffffu, lrow[r], 8);
    }
    #pragma unroll
    for (int r = 0; r < 4; r++) {
        int row = qbase + r0 + r;
        if (row >= NTOK) continue;
        float inv = 1.0f / lrow[r];
        float* op = out + ((size_t)b * NTOK + row) * (2 * DD) + DD + dstart;
        #pragma unroll
        for (int j = 0; j < 8; j += 2) {
            float a, bb, c, d;
            upk2(O2[r][j],     a, bb);
            upk2(O2[r][j + 1], c, d);
            float4 o4 = make_float4(a * inv, bb * inv, c * inv, d * inv);
            *(float4*)(op + (j / 2) * 4) = o4;
        }
    }

    // ---- copy x into out[..., :256] (straight from global; x is L2-hot) ----
    {
        const float* xb = x + ((size_t)b * NTOK + qbase) * DD;
        float* ob = out + ((size_t)b * NTOK + qbase) * (2 * DD);
        for (int idx = tid; idx < BM * (DD / 4); idx += NTHREADS) {
            int d4 = idx & 63;
            int row = idx >> 6;
            if (qbase + row < NTOK)
                *(float4*)(ob + row * (2 * DD) + d4 * 4) =
                    *(const float4*)(xb + row * DD + d4 * 4);
        }
    }
}

// ---------------------------------------------------------------------------
extern "C" void kernel_launch(void* const* d_in, const int* in_sizes, int n_in,
                              void* d_out, int out_size) {
    const float*         x      = (const float*)d_in[0];
    const float*         mem    = (const float*)d_in[1];
    const unsigned char* mask   = (const unsigned char*)d_in[2];
    // d_in[3] = w_lin : unused (constant along softmax axis -> cancels)
    const float*         dscale = (const float*)d_in[4];
    float*               out    = (float*)d_out;

    detect_mask_kernel<<<1, NTHREADS>>>(mask, NB * NTOK);

    const int smem_bytes = (2 * DD * QP + BN * DD + BN + DD) * (int)sizeof(float);
    cudaFuncSetAttribute(attn_kernel, cudaFuncAttributeMaxDynamicSharedMemorySize,
                         smem_bytes);
    dim3 grid(NQT, NB);
    attn_kernel<<<grid, NTHREADS, smem_bytes>>>(x, mem, mask, dscale, out);
}

// round 5
// speedup vs baseline: 1.1481x; 1.1481x over previous
#include <cuda_runtime.h>

// SelfAttention: B=16, n=1764, D=256.
// out[b,n,:256] = x ; out[b,n,256:] = softmax(x*dot_scale @ m^T + mask_bias) @ m
// (w_lin term is constant along softmax axis -> cancels)

#define NB       16
#define NTOK     1764
#define DD       256
#define NPAD     1792        // padded token/key dim (28*64)
#define BMR      48          // query rows per CTA
#define BN       64          // keys per inner tile
#define NQT      37          // 37*48 = 1776 >= 1764 ; 37*16 = 592 = 4*148 CTAs
#define NKT      28
#define KP       64          // k_sT pitch
#define QPITCH   48          // q_sT pitch
#define VP       260         // v_s pitch (float4-aligned, conflict-free octets)
#define PPITCH   64          // P pitch
#define NTHREADS 192

__device__ int g_mask_is4;
__device__ float g_xT[NB][DD][NPAD];    // x^T, pre-scaled by dot_scale
__device__ float g_mT[NB][DD][NPAD];    // mem^T

// ---- packed fp32x2 helpers -------------------------------------------------
__device__ __forceinline__ unsigned long long pk2(float a, float b) {
    unsigned long long r;
    asm("mov.b64 %0, {%1, %2};" : "=l"(r) : "f"(a), "f"(b));
    return r;
}
__device__ __forceinline__ void upk2(unsigned long long v, float& a, float& b) {
    asm("mov.b64 {%0, %1}, %2;" : "=f"(a), "=f"(b) : "l"(v));
}
__device__ __forceinline__ void ffma2(unsigned long long& d, unsigned long long a,
                                      unsigned long long b) {
    asm("fma.rn.f32x2 %0, %1, %2, %0;" : "+l"(d) : "l"(a), "l"(b));
}
__device__ __forceinline__ void fmul2(unsigned long long& d, unsigned long long a,
                                      unsigned long long b) {
    asm("mul.rn.f32x2 %0, %1, %2;" : "+l"(d) : "l"(a), "l"(b));
}

// ---- mask dtype detection --------------------------------------------------
__global__ void detect_mask_kernel(const unsigned char* __restrict__ m, int nbytes) {
    __shared__ int sOdd, sWeird;
    if (threadIdx.x == 0) { sOdd = 0; sWeird = 0; }
    __syncthreads();
    int lodd = 0, lweird = 0;
    for (int i = threadIdx.x; i < nbytes; i += blockDim.x) {
        unsigned char v = m[i];
        if (v > 1) lweird = 1;
        if ((i & 3) && v) lodd = 1;
    }
    if (lodd) sOdd = 1;
    if (lweird) sWeird = 1;
    __syncthreads();
    if (threadIdx.x == 0) g_mask_is4 = ((sOdd == 0) || sWeird) ? 1 : 0;
}

// ---- pre-transpose: g_xT[b][d][tok] = x[b][tok][d]*scale[d]; g_mT likewise --
__global__ void transpose_kernel(const float* __restrict__ x,
                                 const float* __restrict__ mem,
                                 const float* __restrict__ dscale) {
    __shared__ float tile[32][33];
    const int tok0 = blockIdx.x * 32;          // 0..55 -> 1792
    const int d0   = blockIdx.y * 32;          // 0..7  -> 256
    const int b    = blockIdx.z >> 1;
    const bool isX = (blockIdx.z & 1) == 0;
    const float* src = isX ? x : mem;
    const int tx = threadIdx.x, ty = threadIdx.y;   // 32 x 8

    #pragma unroll
    for (int k = 0; k < 4; k++) {
        int tok = tok0 + ty + k * 8;
        float v = 0.f;
        if (tok < NTOK) v = src[((size_t)b * NTOK + tok) * DD + d0 + tx];
        tile[ty + k * 8][tx] = v;
    }
    __syncthreads();
    float* dst = isX ? &g_xT[0][0][0] : &g_mT[0][0][0];
    #pragma unroll
    for (int k = 0; k < 4; k++) {
        int d = d0 + ty + k * 8;
        float v = tile[tx][ty + k * 8];
        if (isX) v *= dscale[d];
        dst[((size_t)b * DD + d) * NPAD + tok0 + tx] = v;
    }
}

// ---------------------------------------------------------------------------
// Flash attention. CTA = (48-row q tile, batch). 192 threads = 6 warps x 8 rows.
// S: lane -> keys {ln, 32+ln} packed in one FFMA2 accumulator.
// O: lane -> dims {4ln..4ln+3, 128+4ln..128+4ln+3}.
// ---------------------------------------------------------------------------
__global__ void __launch_bounds__(NTHREADS, 1)
attn_kernel(const float* __restrict__ x, const float* __restrict__ mem,
            const unsigned char* __restrict__ mask8, float* __restrict__ out)
{
    extern __shared__ float smem[];
    float* q_sT   = smem;                        // [DD][QPITCH]
    float* k_sT   = q_sT + DD * QPITCH;          // [DD][KP]
    float* v_s    = k_sT + DD * KP;              // [BN][VP]
    float* P_s    = v_s + BN * VP;               // [BN][PPITCH] swizzled
    float* bias_s = P_s + BN * PPITCH;           // [BN]

    const int b     = blockIdx.y;
    const int qbase = blockIdx.x * BMR;
    const int tid   = threadIdx.x;
    const int w     = tid >> 5;
    const int ln    = tid & 31;
    const int r0    = w * 8;
    const bool is4  = (g_mask_is4 != 0);
    const int* mask32 = (const int*)mask8;

    // ---- stage Q^T tile once (coalesced from g_xT) ----
    {
        const float* qg = &g_xT[b][0][0] + qbase;
        for (int idx = tid; idx < DD * 12; idx += NTHREADS) {
            int d = idx / 12, r4 = idx - d * 12;
            *(float4*)(q_sT + d * QPITCH + r4 * 4) =
                *(const float4*)(qg + (size_t)d * NPAD + r4 * 4);
        }
    }

    unsigned long long O2[8][4];
    #pragma unroll
    for (int r = 0; r < 8; r++)
        #pragma unroll
        for (int j = 0; j < 4; j++) O2[r][j] = 0ull;
    float mrow[8], lrow[8];
    #pragma unroll
    for (int r = 0; r < 8; r++) { mrow[r] = -1e30f; lrow[r] = 0.f; }

    for (int kt = 0; kt < NKT; kt++) {
        const int kbase = kt * BN;
        __syncthreads();                        // prior S/O done with k_sT,v_s,P_s

        // ---- stage K^T tile (coalesced from g_mT) ----
        {
            const float* kg = &g_mT[b][0][0] + kbase;
            for (int idx = tid; idx < DD * 16; idx += NTHREADS) {
                int d = idx >> 4, c4 = idx & 15;
                *(float4*)(k_sT + d * KP + c4 * 4) =
                    *(const float4*)(kg + (size_t)d * NPAD + c4 * 4);
            }
        }
        // ---- stage V tile natural ----
        {
            const float* mb = mem + ((size_t)b * NTOK + kbase) * DD;
            for (int idx = tid; idx < BN * 64; idx += NTHREADS) {
                int row = idx >> 6, d4 = idx & 63;
                float4 v = make_float4(0.f, 0.f, 0.f, 0.f);
                if (kbase + row < NTOK) v = *(const float4*)(mb + row * DD + d4 * 4);
                *(float4*)(v_s + row * VP + d4 * 4) = v;
            }
        }
        if (tid < BN) {
            int key = kbase + tid;
            float bias = -1e30f;
            if (key < NTOK) {
                int mi = b * NTOK + key;
                bool keep = is4 ? (mask32[mi] != 0) : (mask8[mi] != 0);
                if (keep) bias = 0.f;
            }
            bias_s[tid] = bias;
        }
        __syncthreads();

        // ---- S: 8 rows x key-pair {ln, 32+ln} ----
        unsigned long long acc[8];
        #pragma unroll
        for (int r = 0; r < 8; r++) acc[r] = 0ull;
        {
            const float* kc = k_sT + ln;
            const float* qr = q_sT + r0;
            #pragma unroll 4
            for (int d = 0; d < DD; d++) {
                float kA = kc[d * KP];
                float kB = kc[d * KP + 32];
                unsigned long long k2 = pk2(kA, kB);
                float4 qa = *(const float4*)(qr + d * QPITCH);
                float4 qb = *(const float4*)(qr + d * QPITCH + 4);
                ffma2(acc[0], pk2(qa.x, qa.x), k2);
                ffma2(acc[1], pk2(qa.y, qa.y), k2);
                ffma2(acc[2], pk2(qa.z, qa.z), k2);
                ffma2(acc[3], pk2(qa.w, qa.w), k2);
                ffma2(acc[4], pk2(qb.x, qb.x), k2);
                ffma2(acc[5], pk2(qb.y, qb.y), k2);
                ffma2(acc[6], pk2(qb.z, qb.z), k2);
                ffma2(acc[7], pk2(qb.w, qb.w), k2);
            }
        }

        // ---- online softmax ----
        float s0[8], s1[8];
        float biasA = bias_s[ln], biasB = bias_s[32 + ln];
        #pragma unroll
        for (int r = 0; r < 8; r++) {
            upk2(acc[r], s0[r], s1[r]);
            s0[r] += biasA; s1[r] += biasB;
        }
        #pragma unroll
        for (int r = 0; r < 8; r++) {
            float t = fmaxf(s0[r], s1[r]);
            t = fmaxf(t, __shfl_xor_sync(0xffffffffu, t, 1));
            t = fmaxf(t, __shfl_xor_sync(0xffffffffu, t, 2));
            t = fmaxf(t, __shfl_xor_sync(0xffffffffu, t, 4));
            t = fmaxf(t, __shfl_xor_sync(0xffffffffu, t, 8));
            t = fmaxf(t, __shfl_xor_sync(0xffffffffu, t, 16));
            float mn  = fmaxf(mrow[r], t);
            float scl = __expf(mrow[r] - mn);
            mrow[r] = mn;
            float e0 = __expf(s0[r] - mn);
            float e1 = __expf(s1[r] - mn);
            s0[r] = e0; s1[r] = e1;
            lrow[r] = lrow[r] * scl + e0 + e1;
            unsigned long long s2 = pk2(scl, scl);
            fmul2(O2[r][0], O2[r][0], s2);
            fmul2(O2[r][1], O2[r][1], s2);
            fmul2(O2[r][2], O2[r][2], s2);
            fmul2(O2[r][3], O2[r][3], s2);
        }

        // ---- write P[key][row] swizzled (conflict-free) ----
        {
            const int sw = r0 ^ ((ln & 7) << 3);
            float* pA = P_s + ln * PPITCH + sw;
            *(float4*)(pA)     = make_float4(s0[0], s0[1], s0[2], s0[3]);
            *(float4*)(pA + 4) = make_float4(s0[4], s0[5], s0[6], s0[7]);
            float* pB = P_s + (32 + ln) * PPITCH + sw;
            *(float4*)(pB)     = make_float4(s1[0], s1[1], s1[2], s1[3]);
            *(float4*)(pB + 4) = make_float4(s1[4], s1[5], s1[6], s1[7]);
        }
        __syncthreads();

        // ---- O += P @ V : 8 rows x 8 dims ----
        {
            const float* vbase = v_s + 4 * ln;
            #pragma unroll 2
            for (int k = 0; k < BN; k++) {
                const float* pp = P_s + k * PPITCH + (r0 ^ ((k & 7) << 3));
                float4 pA = *(const float4*)(pp);
                float4 pB = *(const float4*)(pp + 4);
                ulonglong2 vA = *(const ulonglong2*)(vbase + k * VP);
                ulonglong2 vB = *(const ulonglong2*)(vbase + k * VP + 128);
                unsigned long long p0 = pk2(pA.x, pA.x), p1 = pk2(pA.y, pA.y);
                unsigned long long p2 = pk2(pA.z, pA.z), p3 = pk2(pA.w, pA.w);
                unsigned long long p4 = pk2(pB.x, pB.x), p5 = pk2(pB.y, pB.y);
                unsigned long long p6 = pk2(pB.z, pB.z), p7 = pk2(pB.w, pB.w);
                ffma2(O2[0][0], p0, vA.x); ffma2(O2[0][1], p0, vA.y);
                ffma2(O2[0][2], p0, vB.x); ffma2(O2[0][3], p0, vB.y);
                ffma2(O2[1][0], p1, vA.x); ffma2(O2[1][1], p1, vA.y);
                ffma2(O2[1][2], p1, vB.x); ffma2(O2[1][3], p1, vB.y);
                ffma2(O2[2][0], p2, vA.x); ffma2(O2[2][1], p2, vA.y);
                ffma2(O2[2][2], p2, vB.x); ffma2(O2[2][3], p2, vB.y);
                ffma2(O2[3][0], p3, vA.x); ffma2(O2[3][1], p3, vA.y);
                ffma2(O2[3][2], p3, vB.x); ffma2(O2[3][3], p3, vB.y);
                ffma2(O2[4][0], p4, vA.x); ffma2(O2[4][1], p4, vA.y);
                ffma2(O2[4][2], p4, vB.x); ffma2(O2[4][3], p4, vB.y);
                ffma2(O2[5][0], p5, vA.x); ffma2(O2[5][1], p5, vA.y);
                ffma2(O2[5][2], p5, vB.x); ffma2(O2[5][3], p5, vB.y);
                ffma2(O2[6][0], p6, vA.x); ffma2(O2[6][1], p6, vA.y);
                ffma2(O2[6][2], p6, vB.x); ffma2(O2[6][3], p6, vB.y);
                ffma2(O2[7][0], p7, vA.x); ffma2(O2[7][1], p7, vA.y);
                ffma2(O2[7][2], p7, vB.x); ffma2(O2[7][3], p7, vB.y);
            }
        }
    }

    // ---- finalize ----
    #pragma unroll
    for (int r = 0; r < 8; r++) {
        float l = lrow[r];
        l += __shfl_xor_sync(0xffffffffu, l, 1);
        l += __shfl_xor_sync(0xffffffffu, l, 2);
        l += __shfl_xor_sync(0xffffffffu, l, 4);
        l += __shfl_xor_sync(0xffffffffu, l, 8);
        l += __shfl_xor_sync(0xffffffffu, l, 16);
        lrow[r] = l;
    }
    #pragma unroll
    for (int r = 0; r < 8; r++) {
        int row = qbase + r0 + r;
        if (row >= NTOK) continue;
        float inv = 1.0f / lrow[r];
        float* op = out + ((size_t)b * NTOK + row) * (2 * DD) + DD + 4 * ln;
        float a0, a1, a2, a3;
        upk2(O2[r][0], a0, a1); upk2(O2[r][1], a2, a3);
        *(float4*)(op) = make_float4(a0 * inv, a1 * inv, a2 * inv, a3 * inv);
        upk2(O2[r][2], a0, a1); upk2(O2[r][3], a2, a3);
        *(float4*)(op + 128) = make_float4(a0 * inv, a1 * inv, a2 * inv, a3 * inv);
    }

    // ---- copy x into out[..., :256] ----
    {
        const float* xb = x + ((size_t)b * NTOK + qbase) * DD;
        float* ob = out + ((size_t)b * NTOK + qbase) * (2 * DD);
        for (int idx = tid; idx < BMR * 64; idx += NTHREADS) {
            int row = idx >> 6, d4 = idx & 63;
            if (qbase + row < NTOK)
                *(float4*)(ob + row * (2 * DD) + d4 * 4) =
                    *(const float4*)(xb + row * DD + d4 * 4);
        }
    }
}

// ---------------------------------------------------------------------------
extern "C" void kernel_launch(void* const* d_in, const int* in_sizes, int n_in,
                              void* d_out, int out_size) {
    const float*         x      = (const float*)d_in[0];
    const float*         mem    = (const float*)d_in[1];
    const unsigned char* mask   = (const unsigned char*)d_in[2];
    // d_in[3] = w_lin : unused (cancels in softmax)
    const float*         dscale = (const float*)d_in[4];
    float*               out    = (float*)d_out;

    detect_mask_kernel<<<1, 256>>>(mask, NB * NTOK);

    dim3 tgrid(NPAD / 32, DD / 32, NB * 2);
    transpose_kernel<<<tgrid, dim3(32, 8)>>>(x, mem, dscale);

    const int smem_bytes =
        (DD * QPITCH + DD * KP + BN * VP + BN * PPITCH + BN) * (int)sizeof(float);
    cudaFuncSetAttribute(attn_kernel, cudaFuncAttributeMaxDynamicSharedMemorySize,
                         smem_bytes);
    dim3 grid(NQT, NB);
    attn_kernel<<<grid, NTHREADS, smem_bytes>>>(x, mem, mask, out);
}

// round 7
// speedup vs baseline: 1.5968x; 1.3908x over previous
#include <cuda_runtime.h>

// SelfAttention: B=16, n=1764, D=256.
// out[b,n,:256] = x ; out[b,n,256:] = softmax(x*dot_scale @ m^T + mask_bias) @ m
// (w_lin term is constant along the softmax axis -> cancels)

#define NB       16
#define NTOK     1764
#define DD       256
#define BMR      48          // query rows per CTA
#define BN       64          // keys per tile
#define NQT      37          // 37*48=1776 ; 37*16 = 592 CTAs = 4.0 waves on 148 SMs
#define NKT      28
#define QP       260         // q_s pitch (floats), 16B-aligned rows
#define KVP      260         // kv_s pitch
#define PP       100         // P_dup pitch: 2*BMR=96 duplicated floats + 4 pad
#define NTHREADS 384         // 12 warps x 4 rows

__device__ int g_odd, g_weird;

// ---- packed fp32x2 helpers -------------------------------------------------
__device__ __forceinline__ void ffma2(unsigned long long& d, unsigned long long a,
                                      unsigned long long b) {
    asm("fma.rn.f32x2 %0, %1, %2, %0;" : "+l"(d) : "l"(a), "l"(b));
}
__device__ __forceinline__ void fmul2(unsigned long long& d, unsigned long long s) {
    asm("mul.rn.f32x2 %0, %1, %2;" : "+l"(d) : "l"(d), "l"(s));
}
__device__ __forceinline__ unsigned long long add2(unsigned long long a,
                                                   unsigned long long b) {
    unsigned long long r;
    asm("add.rn.f32x2 %0, %1, %2;" : "=l"(r) : "l"(a), "l"(b));
    return r;
}
__device__ __forceinline__ unsigned long long pk2(float a, float b) {
    unsigned long long r;
    asm("mov.b64 %0, {%1, %2};" : "=l"(r) : "f"(a), "f"(b));
    return r;
}
__device__ __forceinline__ void upk2(unsigned long long v, float& a, float& b) {
    asm("mov.b64 {%0, %1}, %2;" : "=f"(a), "=f"(b) : "l"(v));
}

// ---- mask dtype detection (parallel) ---------------------------------------
__global__ void reset_flags_kernel() { g_odd = 0; g_weird = 0; }

__global__ void detect_mask_kernel(const unsigned char* __restrict__ m, int nbytes) {
    int lodd = 0, lweird = 0;
    for (int i = blockIdx.x * blockDim.x + threadIdx.x; i < nbytes;
         i += gridDim.x * blockDim.x) {
        unsigned char v = m[i];
        if (v > 1) lweird = 1;
        if ((i & 3) && v) lodd = 1;
    }
    if (__syncthreads_or(lodd)   && threadIdx.x == 0) atomicOr(&g_odd, 1);
    if (__syncthreads_or(lweird) && threadIdx.x == 0) atomicOr(&g_weird, 1);
}

// ---------------------------------------------------------------------------
// Flash attention. CTA = (48-row q tile, batch). 12 warps x 4 rows.
// S phase packs fp32x2 over the d axis: q and k both read as natural d-pairs
// (no transpose, no dup movs). K and V share one natural-layout smem tile.
// O phase reads a duplicated P tile: (p,p) pairs come straight from smem.
// ---------------------------------------------------------------------------
__global__ void __launch_bounds__(NTHREADS, 1)
attn_kernel(const float* __restrict__ x, const float* __restrict__ mem,
            const unsigned char* __restrict__ mask8,
            const float* __restrict__ dscale, float* __restrict__ out)
{
    extern __shared__ float smem[];
    float* q_s     = smem;                       // [BMR][QP]  x*scale, natural
    float* kv_s    = q_s + BMR * QP;             // [BN][KVP]  mem tile, natural
    float* P_dup   = kv_s + BN * KVP;            // [BN][PP]   probs, duplicated
    float* scale_s = P_dup + BN * PP;            // [DD]
    float* bias_s  = scale_s + DD;               // [BN]

    const int b     = blockIdx.y;
    const int qbase = blockIdx.x * BMR;
    const int tid   = threadIdx.x;
    const int w     = tid >> 5;                  // warp -> rows 4w..4w+3
    const int ln    = tid & 31;                  // lane -> keys {ln, 32+ln}, dims {4ln,128+4ln}
    const bool is4  = (g_odd == 0) || (g_weird != 0);
    const int* mask32 = (const int*)mask8;

    for (int i = tid; i < DD; i += NTHREADS) scale_s[i] = dscale[i];
    __syncthreads();

    // ---- stage Q tile natural, scaled ----
    {
        const float* xb = x + ((size_t)b * NTOK + qbase) * DD;
        for (int idx = tid; idx < BMR * 64; idx += NTHREADS) {
            int row = idx >> 6, d4 = idx & 63;
            float4 v = make_float4(0.f, 0.f, 0.f, 0.f);
            if (qbase + row < NTOK) v = *(const float4*)(xb + row * DD + d4 * 4);
            v.x *= scale_s[d4 * 4];     v.y *= scale_s[d4 * 4 + 1];
            v.z *= scale_s[d4 * 4 + 2]; v.w *= scale_s[d4 * 4 + 3];
            *(float4*)(q_s + row * QP + d4 * 4) = v;
        }
    }

    unsigned long long O2[4][4];                 // [row][dim-pair]
    #pragma unroll
    for (int r = 0; r < 4; r++)
        #pragma unroll
        for (int j = 0; j < 4; j++) O2[r][j] = 0ull;
    float mrow[4], lrow[4];
    #pragma unroll
    for (int r = 0; r < 4; r++) { mrow[r] = -1e30f; lrow[r] = 0.f; }

    for (int kt = 0; kt < NKT; kt++) {
        const int kbase = kt * BN;
        __syncthreads();                          // prior O done with kv_s/P_dup

        // ---- stage mem tile (K and V share it) + bias ----
        {
            const float* mb = mem + ((size_t)b * NTOK + kbase) * DD;
            for (int idx = tid; idx < BN * 64; idx += NTHREADS) {
                int row = idx >> 6, d4 = idx & 63;
                float4 v = make_float4(0.f, 0.f, 0.f, 0.f);
                if (kbase + row < NTOK) v = *(const float4*)(mb + row * DD + d4 * 4);
                *(float4*)(kv_s + row * KVP + d4 * 4) = v;
            }
        }
        if (tid < BN) {
            int key = kbase + tid;
            float bias = -1e30f;
            if (key < NTOK) {
                int mi = b * NTOK + key;
                bool keep = is4 ? (mask32[mi] != 0) : (mask8[mi] != 0);
                if (keep) bias = 0.f;
            }
            bias_s[tid] = bias;
        }
        __syncthreads();

        // ---- S: d-pair-packed dot products, 4 rows x 2 keys ----
        unsigned long long aE[4][2], aO[4][2];
        #pragma unroll
        for (int r = 0; r < 4; r++) {
            aE[r][0] = aE[r][1] = 0ull;
            aO[r][0] = aO[r][1] = 0ull;
        }
        {
            const float* kA = kv_s + ln * KVP;
            const float* kB = kv_s + (32 + ln) * KVP;
            const float* qr = q_s + (w * 4) * QP;
            #pragma unroll 2
            for (int d = 0; d < DD; d += 4) {
                ulonglong2 ka = *(const ulonglong2*)(kA + d);
                ulonglong2 kb = *(const ulonglong2*)(kB + d);
                ulonglong2 q0 = *(const ulonglong2*)(qr + d);
                ulonglong2 q1 = *(const ulonglong2*)(qr + QP + d);
                ulonglong2 q2 = *(const ulonglong2*)(qr + 2 * QP + d);
                ulonglong2 q3 = *(const ulonglong2*)(qr + 3 * QP + d);
                ffma2(aE[0][0], q0.x, ka.x); ffma2(aO[0][0], q0.y, ka.y);
                ffma2(aE[0][1], q0.x, kb.x); ffma2(aO[0][1], q0.y, kb.y);
                ffma2(aE[1][0], q1.x, ka.x); ffma2(aO[1][0], q1.y, ka.y);
                ffma2(aE[1][1], q1.x, kb.x); ffma2(aO[1][1], q1.y, kb.y);
                ffma2(aE[2][0], q2.x, ka.x); ffma2(aO[2][0], q2.y, ka.y);
                ffma2(aE[2][1], q2.x, kb.x); ffma2(aO[2][1], q2.y, kb.y);
                ffma2(aE[3][0], q3.x, ka.x); ffma2(aO[3][0], q3.y, ka.y);
                ffma2(aE[3][1], q3.x, kb.x); ffma2(aO[3][1], q3.y, kb.y);
            }
        }

        // ---- horizontal reduce + bias + online softmax ----
        float s0[4], s1[4];
        float biasA = bias_s[ln], biasB = bias_s[32 + ln];
        #pragma unroll
        for (int r = 0; r < 4; r++) {
            float lo, hi;
            upk2(add2(aE[r][0], aO[r][0]), lo, hi);
            s0[r] = lo + hi + biasA;
            upk2(add2(aE[r][1], aO[r][1]), lo, hi);
            s1[r] = lo + hi + biasB;
        }
        #pragma unroll
        for (int r = 0; r < 4; r++) {
            float t = fmaxf(s0[r], s1[r]);
            t = fmaxf(t, __shfl_xor_sync(0xffffffffu, t, 1));
            t = fmaxf(t, __shfl_xor_sync(0xffffffffu, t, 2));
            t = fmaxf(t, __shfl_xor_sync(0xffffffffu, t, 4));
            t = fmaxf(t, __shfl_xor_sync(0xffffffffu, t, 8));
            t = fmaxf(t, __shfl_xor_sync(0xffffffffu, t, 16));
            float mn  = fmaxf(mrow[r], t);
            float scl = __expf(mrow[r] - mn);
            mrow[r] = mn;
            float e0 = __expf(s0[r] - mn);
            float e1 = __expf(s1[r] - mn);
            s0[r] = e0; s1[r] = e1;
            lrow[r] = lrow[r] * scl + e0 + e1;
            unsigned long long s2 = pk2(scl, scl);
            fmul2(O2[r][0], s2); fmul2(O2[r][1], s2);
            fmul2(O2[r][2], s2); fmul2(O2[r][3], s2);
        }

        // ---- write P duplicated: P_dup[key][8w..8w+7] = (p0,p0,p1,p1,...) ----
        {
            float* pA = P_dup + ln * PP + 8 * w;
            *(float4*)(pA)     = make_float4(s0[0], s0[0], s0[1], s0[1]);
            *(float4*)(pA + 4) = make_float4(s0[2], s0[2], s0[3], s0[3]);
            float* pB = P_dup + (32 + ln) * PP + 8 * w;
            *(float4*)(pB)     = make_float4(s1[0], s1[0], s1[1], s1[1]);
            *(float4*)(pB + 4) = make_float4(s1[2], s1[2], s1[3], s1[3]);
        }
        __syncthreads();

        // ---- O += P @ V : zero movs (dup pairs from P_dup, d-pairs from kv) ----
        {
            const float* vb = kv_s + 4 * ln;
            const float* pb = P_dup + 8 * w;
            #pragma unroll 2
            for (int k = 0; k < BN; k++) {
                ulonglong2 pd  = *(const ulonglong2*)(pb + k * PP);      // (p0,p0)(p1,p1)
                ulonglong2 pd2 = *(const ulonglong2*)(pb + k * PP + 4);  // (p2,p2)(p3,p3)
                ulonglong2 vA  = *(const ulonglong2*)(vb + k * KVP);       // dims 4ln..
                ulonglong2 vB  = *(const ulonglong2*)(vb + k * KVP + 128); // dims 128+4ln..
                ffma2(O2[0][0], pd.x,  vA.x); ffma2(O2[0][1], pd.x,  vA.y);
                ffma2(O2[0][2], pd.x,  vB.x); ffma2(O2[0][3], pd.x,  vB.y);
                ffma2(O2[1][0], pd.y,  vA.x); ffma2(O2[1][1], pd.y,  vA.y);
                ffma2(O2[1][2], pd.y,  vB.x); ffma2(O2[1][3], pd.y,  vB.y);
                ffma2(O2[2][0], pd2.x, vA.x); ffma2(O2[2][1], pd2.x, vA.y);
                ffma2(O2[2][2], pd2.x, vB.x); ffma2(O2[2][3], pd2.x, vB.y);
                ffma2(O2[3][0], pd2.y, vA.x); ffma2(O2[3][1], pd2.y, vA.y);
                ffma2(O2[3][2], pd2.y, vB.x); ffma2(O2[3][3], pd2.y, vB.y);
            }
        }
    }

    // ---- finalize ----
    #pragma unroll
    for (int r = 0; r < 4; r++) {
        float l = lrow[r];
        l += __shfl_xor_sync(0xffffffffu, l, 1);
        l += __shfl_xor_sync(0xffffffffu, l, 2);
        l += __shfl_xor_sync(0xffffffffu, l, 4);
        l += __shfl_xor_sync(0xffffffffu, l, 8);
        l += __shfl_xor_sync(0xffffffffu, l, 16);
        lrow[r] = l;
    }
    #pragma unroll
    for (int r = 0; r < 4; r++) {
        int row = qbase + 4 * w + r;
        if (row >= NTOK) continue;
        float inv = 1.0f / lrow[r];
        float* op = out + ((size_t)b * NTOK + row) * (2 * DD) + DD + 4 * ln;
        float a0, a1, a2, a3;
        upk2(O2[r][0], a0, a1); upk2(O2[r][1], a2, a3);
        *(float4*)(op) = make_float4(a0 * inv, a1 * inv, a2 * inv, a3 * inv);
        upk2(O2[r][2], a0, a1); upk2(O2[r][3], a2, a3);
        *(float4*)(op + 128) = make_float4(a0 * inv, a1 * inv, a2 * inv, a3 * inv);
    }

    // ---- copy x into out[..., :256] ----
    {
        const float* xb = x + ((size_t)b * NTOK + qbase) * DD;
        float* ob = out + ((size_t)b * NTOK + qbase) * (2 * DD);
        for (int idx = tid; idx < BMR * 64; idx += NTHREADS) {
            int row = idx >> 6, d4 = idx & 63;
            if (qbase + row < NTOK)
                *(float4*)(ob + row * (2 * DD) + d4 * 4) =
                    *(const float4*)(xb + row * DD + d4 * 4);
        }
    }
}

// ---------------------------------------------------------------------------
extern "C" void kernel_launch(void* const* d_in, const int* in_sizes, int n_in,
                              void* d_out, int out_size) {
    const float*         x      = (const float*)d_in[0];
    const float*         mem    = (const float*)d_in[1];
    const unsigned char* mask   = (const unsigned char*)d_in[2];
    // d_in[3] = w_lin : unused (cancels in softmax)
    const float*         dscale = (const float*)d_in[4];
    float*               out    = (float*)d_out;

    reset_flags_kernel<<<1, 1>>>();
    detect_mask_kernel<<<56, 256>>>(mask, NB * NTOK);

    const int smem_bytes =
        (BMR * QP + BN * KVP + BN * PP + DD + BN) * (int)sizeof(float);
    cudaFuncSetAttribute(attn_kernel, cudaFuncAttributeMaxDynamicSharedMemorySize,
                         smem_bytes);
    dim3 grid(NQT, NB);
    attn_kernel<<<grid, NTHREADS, smem_bytes>>>(x, mem, mask, dscale, out);
}